// round 2
// baseline (speedup 1.0000x reference)
#include <cuda_runtime.h>

// Problem constants
#define N_B    64
#define T_LEN  2048
#define IN_D   8
#define C_CH   2
#define M_D    10
#define STEPS  2047          // T-1 increments
#define LCHUNK 64            // time steps per warp-chunk
#define NCHUNK 32            // chunks per (n,c) chain  (32*64 = 2048 >= 2047)
#define WPB    4             // warps per block
#define NWARPS (N_B * C_CH * NCHUNK)   // 4096 warp-jobs

// Scratch for per-chunk partial products (128 chains * 32 chunks * 100 floats)
__device__ float g_part[NWARPS * 100];

// 2x2-tile of a 10x10 matmul: O[r0..r0+1][c0..c0+1] = A @ B
__device__ __forceinline__ void mm22(const float* __restrict__ Am,
                                     const float* __restrict__ Bm,
                                     int r0, int c0,
                                     float& o00, float& o01, float& o10, float& o11) {
    o00 = 0.f; o01 = 0.f; o10 = 0.f; o11 = 0.f;
#pragma unroll
    for (int i = 0; i < 10; ++i) {
        float a0 = Am[r0 * 10 + i];
        float a1 = Am[r0 * 10 + 10 + i];
        float2 b = *(const float2*)(Bm + i * 10 + c0);
        o00 = fmaf(a0, b.x, o00);
        o01 = fmaf(a0, b.y, o01);
        o10 = fmaf(a1, b.x, o10);
        o11 = fmaf(a1, b.y, o11);
    }
}

__device__ __forceinline__ void st22(float* __restrict__ Bm, int r0, int c0,
                                     float v00, float v01, float v10, float v11) {
    *(float2*)(Bm + r0 * 10 + c0)      = make_float2(v00, v01);
    *(float2*)(Bm + r0 * 10 + 10 + c0) = make_float2(v10, v11);
}

// ---------------------------------------------------------------------------
// Kernel 1: each WARP owns one (n, c, chunk) and computes the ordered product
// of exp(G_t) over its 64 time steps. All inter-phase sync is __syncwarp().
// ---------------------------------------------------------------------------
__global__ void __launch_bounds__(128) step_kernel(const float* __restrict__ x,
                                                   const float* __restrict__ A) {
    __shared__ __align__(16) float sk[C_CH * IN_D * 100];        // skew generators
    __shared__ __align__(16) float xs[WPB][(LCHUNK + 1) * IN_D]; // per-warp x slice
    __shared__ __align__(16) float buf[WPB][7][100];             // per-warp matrices

    int tid = threadIdx.x;

    // Build skew = A - A^T into shared (whole block cooperates)
    for (int idx = tid; idx < C_CH * IN_D * 100; idx += 128) {
        int jk = idx % 100;
        int ci = idx / 100;           // c*IN_D + i
        int j = jk / 10, k = jk % 10;
        sk[idx] = A[ci * 100 + j * 10 + k] - A[ci * 100 + k * 10 + j];
    }

    int warp = tid >> 5, lane = tid & 31;
    int w     = blockIdx.x * WPB + warp;       // global warp-job id [0, 4096)
    int chunk = w & (NCHUNK - 1);
    int c     = (w >> 5) & 1;
    int n     = w >> 6;
    int t0    = chunk * LCHUNK;
    int nsteps = min(LCHUNK, STEPS - t0);

    // Load x[n, t0 .. t0+nsteps, :] (nsteps+1 rows) into shared
    const float* xp = x + ((size_t)n * T_LEN + t0) * IN_D;
    int cnt = (nsteps + 1) * IN_D;
    for (int idx = lane; idx < cnt; idx += 32) xs[warp][idx] = xp[idx];
    __syncthreads();   // skew ready for everyone

    bool act = lane < 25;
    int j2 = lane / 5, k2 = lane % 5;
    int r0 = 2 * j2, c0 = 2 * k2;
    float dI = (act && j2 == k2) ? 1.f : 0.f;  // identity contribution of this tile's diagonal

    float* bG  = buf[warp][0];
    float* bW  = buf[warp][1];
    float* bW2 = buf[warp][2];
    float* bS  = buf[warp][3];
    float* bE  = buf[warp][4];
    float* bA0 = buf[warp][5];
    float* bA1 = buf[warp][6];
    const float* skc = sk + c * IN_D * 100;
    const float* xw  = xs[warp];

    // Acc = I
    if (act) st22(bA0, r0, c0, dI, 0.f, 0.f, dI);
    __syncwarp();

    float* accA = bA0;
    float* accB = bA1;

    for (int t = 0; t < nsteps; ++t) {
        // ---- Phase 1: G = 0.25 * sum_i dx_i * skew[c,i]  (pre-scaled by 2^-2) ----
        if (act) {
            float g00 = 0.f, g01 = 0.f, g10 = 0.f, g11 = 0.f;
#pragma unroll
            for (int i = 0; i < IN_D; ++i) {
                float dx = 0.25f * (xw[(t + 1) * IN_D + i] - xw[t * IN_D + i]);
                float2 a0 = *(const float2*)(skc + i * 100 + r0 * 10 + c0);
                float2 a1 = *(const float2*)(skc + i * 100 + r0 * 10 + 10 + c0);
                g00 = fmaf(dx, a0.x, g00);
                g01 = fmaf(dx, a0.y, g01);
                g10 = fmaf(dx, a1.x, g10);
                g11 = fmaf(dx, a1.y, g11);
            }
            st22(bG, r0, c0, g00, g01, g10, g11);
        }
        __syncwarp();

        // ---- Phase 2: W = G @ G  (symmetric) ----
        float w00, w01, w10, w11;
        if (act) { mm22(bG, bG, r0, c0, w00, w01, w10, w11);
                   st22(bW, r0, c0, w00, w01, w10, w11); }
        __syncwarp();

        // ---- Phase 3: W2 = W @ W ----
        float p00, p01, p10, p11;
        if (act) { mm22(bW, bW, r0, c0, p00, p01, p10, p11);
                   st22(bW2, r0, c0, p00, p01, p10, p11); }
        __syncwarp();

        // ---- Phase 4: Taylor combos; W3, W4 register-only ----
        float C00 = 0.f, C01 = 0.f, C10 = 0.f, C11 = 0.f;
        if (act) {
            const float c2 = 0.5f,        c4 = 1.f / 24.f;
            const float c6 = 1.f / 720.f, c8 = 1.f / 40320.f;
            const float s2 = 1.f / 6.f,    s4 = 1.f / 120.f;
            const float s6 = 1.f / 5040.f, s8 = 1.f / 362880.f;

            C00 = dI + c2 * w00 + c4 * p00;  C01 = c2 * w01 + c4 * p01;
            C10 =      c2 * w10 + c4 * p10;  C11 = dI + c2 * w11 + c4 * p11;
            float S00 = dI + s2 * w00 + s4 * p00, S01 = s2 * w01 + s4 * p01;
            float S10 =      s2 * w10 + s4 * p10, S11 = dI + s2 * w11 + s4 * p11;

            float x00, x01, x10, x11;
            mm22(bW2, bW, r0, c0, x00, x01, x10, x11);   // W3 (reads only, no sync needed)
            C00 += c6 * x00; C01 += c6 * x01; C10 += c6 * x10; C11 += c6 * x11;
            S00 += s6 * x00; S01 += s6 * x01; S10 += s6 * x10; S11 += s6 * x11;

            mm22(bW2, bW2, r0, c0, x00, x01, x10, x11);  // W4
            C00 += c8 * x00; C01 += c8 * x01; C10 += c8 * x10; C11 += c8 * x11;
            S00 += s8 * x00; S01 += s8 * x01; S10 += s8 * x10; S11 += s8 * x11;

            st22(bS, r0, c0, S00, S01, S10, S11);
        }
        __syncwarp();

        // ---- Phase 5: E = C + G @ Spoly ----
        float e00, e01, e10, e11;
        if (act) {
            mm22(bG, bS, r0, c0, e00, e01, e10, e11);
            e00 += C00; e01 += C01; e10 += C10; e11 += C11;
            st22(bE, r0, c0, e00, e01, e10, e11);
        }
        __syncwarp();

        // ---- Squaring 1: bW = E @ E ----
        if (act) { mm22(bE, bE, r0, c0, w00, w01, w10, w11);
                   st22(bW, r0, c0, w00, w01, w10, w11); }
        __syncwarp();

        // ---- Squaring 2: bE = (E^2) @ (E^2) ----
        if (act) { mm22(bW, bW, r0, c0, e00, e01, e10, e11);
                   st22(bE, r0, c0, e00, e01, e10, e11); }
        __syncwarp();

        // ---- Chain: Acc = Acc @ exp(G) ----
        if (act) {
            float a00, a01, a10, a11;
            mm22(accA, bE, r0, c0, a00, a01, a10, a11);
            st22(accB, r0, c0, a00, a01, a10, a11);
        }
        __syncwarp();
        float* tmp = accA; accA = accB; accB = tmp;
    }

    // Write partial product for this chunk
    float* pp = g_part + (size_t)w * 100;
    if (act) {
        *(float2*)(pp + r0 * 10 + c0)      = *(const float2*)(accA + r0 * 10 + c0);
        *(float2*)(pp + r0 * 10 + 10 + c0) = *(const float2*)(accA + r0 * 10 + 10 + c0);
    }
}

// ---------------------------------------------------------------------------
// Kernel 2: per (n,c) chain, multiply the 32 chunk partials in order.
// ---------------------------------------------------------------------------
__global__ void __launch_bounds__(32) combine_kernel(float* __restrict__ out) {
    __shared__ __align__(16) float P[100];
    __shared__ __align__(16) float Ac[2][100];

    int lane = threadIdx.x;
    int nc = blockIdx.x;                   // n*C + c, 0..127
    bool act = lane < 25;
    int j2 = lane / 5, k2 = lane % 5;
    int r0 = 2 * j2, c0 = 2 * k2;

    const float* base = g_part + (size_t)nc * NCHUNK * 100;
    for (int idx = lane; idx < 100; idx += 32) Ac[0][idx] = base[idx];
    __syncwarp();

    int cur = 0;
    for (int p = 1; p < NCHUNK; ++p) {
        for (int idx = lane; idx < 100; idx += 32) P[idx] = base[p * 100 + idx];
        __syncwarp();
        float o00, o01, o10, o11;
        if (act) {
            mm22(Ac[cur], P, r0, c0, o00, o01, o10, o11);
            st22(Ac[cur ^ 1], r0, c0, o00, o01, o10, o11);
        }
        __syncwarp();
        cur ^= 1;
    }

    float* o = out + (size_t)nc * 100;
    for (int idx = lane; idx < 100; idx += 32) o[idx] = Ac[cur][idx];
}

extern "C" void kernel_launch(void* const* d_in, const int* in_sizes, int n_in,
                              void* d_out, int out_size) {
    const float* x = (const float*)d_in[0];
    const float* A = (const float*)d_in[1];
    // Defensive: x (1,048,576 elems) is the big input, A (1600) the small one.
    if (n_in >= 2 && in_sizes[0] < in_sizes[1]) {
        const float* t = x; x = A; A = t;
    }

    step_kernel<<<NWARPS / WPB, 128>>>(x, A);          // 1024 blocks x 128 threads
    combine_kernel<<<N_B * C_CH, 32>>>((float*)d_out); // 128 blocks x 1 warp
}

// round 5
// speedup vs baseline: 1.5110x; 1.5110x over previous
#include <cuda_runtime.h>

#define N_B    64
#define T_LEN  2048
#define IN_D   8
#define C_CH   2
#define STEPS  2047
#define LCHUNK 32            // time steps per warp-chunk
#define NCHUNK 64            // chunks per chain (64*32 = 2048 >= 2047)
#define WPB    4
#define NCHAIN (N_B * C_CH)              // 128
#define NWARPS (NCHAIN * NCHUNK)         // 8192

__device__ __align__(16) float g_part [NWARPS * 100];
__device__ __align__(16) float g_part2[NCHAIN * 8 * 100];

// 2x2 tile of 10x10 matmul, float2 loads on both operands (20 LDS + 40 FFMA)
__device__ __forceinline__ void mm22(const float* __restrict__ Am,
                                     const float* __restrict__ Bm,
                                     int r0, int c0,
                                     float& o00, float& o01, float& o10, float& o11) {
    o00 = 0.f; o01 = 0.f; o10 = 0.f; o11 = 0.f;
#pragma unroll
    for (int i = 0; i < 10; i += 2) {
        float2 a0 = *(const float2*)(Am + r0 * 10 + i);
        float2 a1 = *(const float2*)(Am + r0 * 10 + 10 + i);
        float2 b0 = *(const float2*)(Bm + i * 10 + c0);
        float2 b1 = *(const float2*)(Bm + (i + 1) * 10 + c0);
        o00 = fmaf(a0.x, b0.x, o00); o00 = fmaf(a0.y, b1.x, o00);
        o01 = fmaf(a0.x, b0.y, o01); o01 = fmaf(a0.y, b1.y, o01);
        o10 = fmaf(a1.x, b0.x, o10); o10 = fmaf(a1.y, b1.x, o10);
        o11 = fmaf(a1.x, b0.y, o11); o11 = fmaf(a1.y, b1.y, o11);
    }
}

// Dual matmul sharing A-row loads: C += A@B1, S += A@B2  (30 LDS + 80 FFMA)
__device__ __forceinline__ void mm22_dual(const float* __restrict__ Am,
                                          const float* __restrict__ B1,
                                          const float* __restrict__ B2,
                                          int r0, int c0,
                                          float& c00, float& c01, float& c10, float& c11,
                                          float& s00, float& s01, float& s10, float& s11) {
#pragma unroll
    for (int i = 0; i < 10; i += 2) {
        float2 a0 = *(const float2*)(Am + r0 * 10 + i);
        float2 a1 = *(const float2*)(Am + r0 * 10 + 10 + i);
        float2 x0 = *(const float2*)(B1 + i * 10 + c0);
        float2 x1 = *(const float2*)(B1 + (i + 1) * 10 + c0);
        float2 y0 = *(const float2*)(B2 + i * 10 + c0);
        float2 y1 = *(const float2*)(B2 + (i + 1) * 10 + c0);
        c00 = fmaf(a0.x, x0.x, c00); c00 = fmaf(a0.y, x1.x, c00);
        c01 = fmaf(a0.x, x0.y, c01); c01 = fmaf(a0.y, x1.y, c01);
        c10 = fmaf(a1.x, x0.x, c10); c10 = fmaf(a1.y, x1.x, c10);
        c11 = fmaf(a1.x, x0.y, c11); c11 = fmaf(a1.y, x1.y, c11);
        s00 = fmaf(a0.x, y0.x, s00); s00 = fmaf(a0.y, y1.x, s00);
        s01 = fmaf(a0.x, y0.y, s01); s01 = fmaf(a0.y, y1.y, s01);
        s10 = fmaf(a1.x, y0.x, s10); s10 = fmaf(a1.y, y1.x, s10);
        s11 = fmaf(a1.x, y0.y, s11); s11 = fmaf(a1.y, y1.y, s11);
    }
}

__device__ __forceinline__ void st22(float* __restrict__ Bm, int r0, int c0,
                                     float v00, float v01, float v10, float v11) {
    *(float2*)(Bm + r0 * 10 + c0)      = make_float2(v00, v01);
    *(float2*)(Bm + r0 * 10 + 10 + c0) = make_float2(v10, v11);
}

// ---------------------------------------------------------------------------
// Kernel 1: one warp per (chain, chunk): ordered product of exp(G_t) over
// 32 time steps. Order-9 Taylor, no scaling/squaring (theta ~ 0.45).
// ---------------------------------------------------------------------------
__global__ void __launch_bounds__(128) step_kernel(const float* __restrict__ x,
                                                   const float* __restrict__ A) {
    __shared__ __align__(16) float sk[C_CH * IN_D * 100];         // skew generators
    __shared__ __align__(16) float xs[WPB][(LCHUNK + 1) * IN_D];  // x slice
    __shared__ __align__(16) float dxs[WPB][LCHUNK * IN_D];       // increments
    __shared__ __align__(16) float buf[WPB][9][100];              // matrices

    int tid = threadIdx.x;

    // skew = A - A^T
    for (int idx = tid; idx < C_CH * IN_D * 100; idx += 128) {
        int jk = idx % 100;
        int ci = idx / 100;
        int j = jk / 10, k = jk % 10;
        sk[idx] = A[ci * 100 + j * 10 + k] - A[ci * 100 + k * 10 + j];
    }

    int warp = tid >> 5, lane = tid & 31;
    int w     = blockIdx.x * WPB + warp;     // [0, 8192)
    int chunk = w & (NCHUNK - 1);
    int chain = w >> 6;                      // n*2 + c
    int c     = chain & 1;
    int n     = chain >> 1;
    int t0    = chunk * LCHUNK;
    int nsteps = min(LCHUNK, STEPS - t0);

    const float* xp = x + ((size_t)n * T_LEN + t0) * IN_D;
    float* xw = xs[warp];
    int cnt = (nsteps + 1) * IN_D;
    for (int idx = lane; idx < cnt; idx += 32) xw[idx] = xp[idx];
    __syncthreads();   // sk + xw ready

    // dx into separate buffer (no in-place hazard)
    float* dxp = dxs[warp];
    for (int idx = lane; idx < nsteps * IN_D; idx += 32)
        dxp[idx] = xw[idx + IN_D] - xw[idx];

    bool act = lane < 25;
    int l  = act ? lane : 0;
    int j2 = l / 5, k2 = l % 5;
    int r0 = 2 * j2, c0 = 2 * k2;
    float dI = (act && j2 == k2) ? 1.f : 0.f;

    // skew tiles -> registers (32 regs)
    const float* skc = sk + c * IN_D * 100;
    float ska[IN_D][4];
#pragma unroll
    for (int i = 0; i < IN_D; ++i) {
        float2 a0 = *(const float2*)(skc + i * 100 + r0 * 10 + c0);
        float2 a1 = *(const float2*)(skc + i * 100 + r0 * 10 + 10 + c0);
        ska[i][0] = a0.x; ska[i][1] = a0.y; ska[i][2] = a1.x; ska[i][3] = a1.y;
    }

    float* bG  = buf[warp][0];
    float* bW  = buf[warp][1];
    float* bW2 = buf[warp][2];
    float* bX  = buf[warp][3];
    float* bY  = buf[warp][4];
    float* bS  = buf[warp][5];
    float* bE  = buf[warp][6];
    float* bA0 = buf[warp][7];
    float* bA1 = buf[warp][8];

    if (act) st22(bA0, r0, c0, dI, 0.f, 0.f, dI);   // Acc = I
    __syncwarp();

    float* accA = bA0;
    float* accB = bA1;

    const float c2 = 0.5f,         c4 = 1.f / 24.f;
    const float c6 = 1.f / 720.f,  c8 = 1.f / 40320.f;
    const float s2 = 1.f / 6.f,    s4 = 1.f / 120.f;
    const float s6 = 1.f / 5040.f, s8 = 1.f / 362880.f;

    for (int t = 0; t < nsteps; ++t) {
        // G = sum_i dx_i * skew_i   (skew in regs, dx broadcast from shared)
        float g00 = 0.f, g01 = 0.f, g10 = 0.f, g11 = 0.f;
        const float* d = dxp + t * IN_D;
#pragma unroll
        for (int i = 0; i < IN_D; i += 2) {
            float2 dx2 = *(const float2*)(d + i);
            g00 = fmaf(dx2.x, ska[i][0], g00);     g01 = fmaf(dx2.x, ska[i][1], g01);
            g10 = fmaf(dx2.x, ska[i][2], g10);     g11 = fmaf(dx2.x, ska[i][3], g11);
            g00 = fmaf(dx2.y, ska[i + 1][0], g00); g01 = fmaf(dx2.y, ska[i + 1][1], g01);
            g10 = fmaf(dx2.y, ska[i + 1][2], g10); g11 = fmaf(dx2.y, ska[i + 1][3], g11);
        }
        if (act) st22(bG, r0, c0, g00, g01, g10, g11);
        __syncwarp();

        // W = G @ G
        float w00, w01, w10, w11;
        mm22(bG, bG, r0, c0, w00, w01, w10, w11);
        if (act) st22(bW, r0, c0, w00, w01, w10, w11);
        __syncwarp();

        // W2 = W @ W ; X = c6*W + c8*W2 ; Y = s6*W + s8*W2 (elementwise, reg tiles)
        float p00, p01, p10, p11;
        mm22(bW, bW, r0, c0, p00, p01, p10, p11);
        if (act) {
            st22(bW2, r0, c0, p00, p01, p10, p11);
            st22(bX, r0, c0, fmaf(c8, p00, c6 * w00), fmaf(c8, p01, c6 * w01),
                             fmaf(c8, p10, c6 * w10), fmaf(c8, p11, c6 * w11));
            st22(bY, r0, c0, fmaf(s8, p00, s6 * w00), fmaf(s8, p01, s6 * w01),
                             fmaf(s8, p10, s6 * w10), fmaf(s8, p11, s6 * w11));
        }
        // low-order parts in registers
        float C00 = dI + fmaf(c2, w00, c4 * p00), C01 = fmaf(c2, w01, c4 * p01);
        float C10 =      fmaf(c2, w10, c4 * p10), C11 = dI + fmaf(c2, w11, c4 * p11);
        float S00 = dI + fmaf(s2, w00, s4 * p00), S01 = fmaf(s2, w01, s4 * p01);
        float S10 =      fmaf(s2, w10, s4 * p10), S11 = dI + fmaf(s2, w11, s4 * p11);
        __syncwarp();

        // C += W2 @ X ; S += W2 @ Y   (shared A-row loads)
        mm22_dual(bW2, bX, bY, r0, c0, C00, C01, C10, C11, S00, S01, S10, S11);
        if (act) st22(bS, r0, c0, S00, S01, S10, S11);
        __syncwarp();

        // E = C + G @ S
        float e00, e01, e10, e11;
        mm22(bG, bS, r0, c0, e00, e01, e10, e11);
        e00 += C00; e01 += C01; e10 += C10; e11 += C11;
        if (act) st22(bE, r0, c0, e00, e01, e10, e11);
        __syncwarp();

        // Acc = Acc @ E
        float a00, a01, a10, a11;
        mm22(accA, bE, r0, c0, a00, a01, a10, a11);
        if (act) st22(accB, r0, c0, a00, a01, a10, a11);
        __syncwarp();
        float* tmp = accA; accA = accB; accB = tmp;
    }

    if (act) {
        float4 v = *(const float4*)(accA + lane * 4);
        *(float4*)(g_part + (size_t)w * 100 + lane * 4) = v;
    }
}

// ---------------------------------------------------------------------------
// Tree combine: one warp multiplies `cntp` consecutive partials in order.
// ---------------------------------------------------------------------------
__device__ __forceinline__ void combine_run(const float* __restrict__ src,
                                            float* __restrict__ dst,
                                            float* Ac0, float* Ac1, float* Pb,
                                            int lane, int cntp) {
    bool act = lane < 25;
    int l  = act ? lane : 0;
    int j2 = l / 5, k2 = l % 5;
    int r0 = 2 * j2, c0 = 2 * k2;

    if (act) *(float4*)(Ac0 + lane * 4) = *(const float4*)(src + lane * 4);
    __syncwarp();

    float* cur = Ac0;
    float* nxt = Ac1;
    for (int p = 1; p < cntp; ++p) {
        if (act) *(float4*)(Pb + lane * 4) = *(const float4*)(src + p * 100 + lane * 4);
        __syncwarp();
        float o00, o01, o10, o11;
        mm22(cur, Pb, r0, c0, o00, o01, o10, o11);
        if (act) st22(nxt, r0, c0, o00, o01, o10, o11);
        __syncwarp();
        float* tmp = cur; cur = nxt; nxt = tmp;
    }
    if (act) *(float4*)(dst + lane * 4) = *(const float4*)(cur + lane * 4);
}

__global__ void __launch_bounds__(128) combineA() {
    __shared__ __align__(16) float sm[WPB][3][100];
    int warp = threadIdx.x >> 5, lane = threadIdx.x & 31;
    int w = blockIdx.x * WPB + warp;          // [0, 1024)
    int chain = w >> 3, g = w & 7;
    combine_run(g_part + ((size_t)chain * NCHUNK + g * 8) * 100,
                g_part2 + ((size_t)chain * 8 + g) * 100,
                sm[warp][0], sm[warp][1], sm[warp][2], lane, 8);
}

__global__ void __launch_bounds__(128) combineB(float* __restrict__ out) {
    __shared__ __align__(16) float sm[WPB][3][100];
    int warp = threadIdx.x >> 5, lane = threadIdx.x & 31;
    int chain = blockIdx.x * WPB + warp;      // [0, 128)
    combine_run(g_part2 + (size_t)chain * 8 * 100,
                out + (size_t)chain * 100,
                sm[warp][0], sm[warp][1], sm[warp][2], lane, 8);
}

extern "C" void kernel_launch(void* const* d_in, const int* in_sizes, int n_in,
                              void* d_out, int out_size) {
    const float* x = (const float*)d_in[0];
    const float* A = (const float*)d_in[1];
    if (n_in >= 2 && in_sizes[0] < in_sizes[1]) {
        const float* t = x; x = A; A = t;
    }

    step_kernel<<<NWARPS / WPB, 128>>>(x, A);   // 2048 blocks
    combineA<<<1024 / WPB, 128>>>();            // 256 blocks
    combineB<<<128 / WPB, 128>>>((float*)d_out);// 32 blocks
}